// round 2
// baseline (speedup 1.0000x reference)
#include <cuda_runtime.h>
#include <math.h>

#define BATCH 4
#define SEQ   1024
#define DMOD  256
#define DST   64
#define NTOK  (BATCH*SEQ)   // 4096 tokens

// ---------------- scratch (static __device__ — no allocs allowed) ----------------
__device__ float g_A[NTOK * DST * DST];     // 64 MB: exp(logD)-scaled A, [token][i*64+j]
__device__ float g_expD[NTOK * DST];        // exp(x@WD + bD)
__device__ float g_BxPart[NTOK * DST * 2];  // partial Bx, [token][n*2+p]
__device__ float g_h[NTOK * DST];           // recurrence states, [token][n]

// ---------------- GEMM template ----------------
// All: M = 4096 tokens. BM = TM*16, BN = 128, BK = 16, 256 threads, (TM x 8)/thread
// as 2x2 blocks of 4x4 split at +-64 (conflict-free LDS.128 phases).
// MODE 1: g_A = (X@WA + bA) * expD          (N = 4096,  TM = 8)
// MODE 2: Bx partials from (X@WB + bB)      (N = 16384, TM = 8; Bm never stored)
// MODE 4: out = Y@WCr (+ h@bC fold)         (virtual K = 16448, TM = 4)
//         Y[t, n*256+k] = h[t,n]*x[t,k] built on the fly; WCr is an index remap of WC.
template<int MODE, int N, int TM>
__global__ __launch_bounds__(256)
void gemm_kernel(const float* __restrict__ X, const float* __restrict__ W,
                 const float* __restrict__ bias, float* __restrict__ Out)
{
    constexpr int BM = TM * 16;
    constexpr int BK = 16;
    constexpr int BN = 128;
    __shared__ float As[BM * 17];                    // [m][k] padded stride 17
    __shared__ float Bs[BK * BN];                    // [k][n]
    __shared__ float Red[(MODE == 2) ? BM * 16 : 1];

    const int tid = threadIdx.x;
    const int t0  = blockIdx.y * BM;
    const int c0  = blockIdx.x * BN;
    const int tx  = tid & 15;
    const int ty  = tid >> 4;

    float acc[TM][8];
#pragma unroll
    for (int i = 0; i < TM; i++)
#pragma unroll
        for (int j = 0; j < 8; j++) acc[i][j] = 0.f;

    constexpr int KTOT = (MODE == 4) ? (16384 + 64) : DMOD;

    for (int k0 = 0; k0 < KTOT; k0 += BK) {
        // ---- A tile (transposed-ish store, pad 17) ----
        if constexpr (MODE == 4) {
            // BM=64: one float4 per thread; Y built on the fly from h and x
            int m = tid >> 2, kq = tid & 3;
            float4 v;
            if (k0 < 16384) {
                float hv  = g_h[(t0 + m) * DST + (k0 >> 8)];
                float4 xv = *(const float4*)(X + (t0 + m) * DMOD + (k0 & 255) + kq * 4);
                v = make_float4(hv * xv.x, hv * xv.y, hv * xv.z, hv * xv.w);
            } else {
                // bias-fold region: Y[t, 16384+n] = h[t,n]
                v = *(const float4*)(g_h + (t0 + m) * DST + (k0 - 16384) + kq * 4);
            }
            float* a = As + m * 17 + kq * 4;
            a[0] = v.x; a[1] = v.y; a[2] = v.z; a[3] = v.w;
        } else {
#pragma unroll
            for (int q = 0; q < 2; q++) {
                int idx = tid + 256 * q;
                int m = idx >> 2, kq = idx & 3;
                float4 v = *(const float4*)(X + (t0 + m) * DMOD + k0 + kq * 4);
                float* a = As + m * 17 + kq * 4;
                a[0] = v.x; a[1] = v.y; a[2] = v.z; a[3] = v.w;
            }
        }
        // ---- B tile ----
#pragma unroll
        for (int q = 0; q < 2; q++) {
            int idx = tid + 256 * q;
            int kk = idx >> 5, cc = (idx & 31) * 4;
            const float* src;
            if constexpr (MODE == 4) {
                if (k0 < 16384)
                    src = W + (size_t)((k0 & 255) + kk) * 16384 + (k0 >> 8) * 256 + c0 + cc;
                else
                    src = bias + (size_t)(k0 - 16384 + kk) * 256 + c0 + cc;
            } else {
                src = W + (size_t)(k0 + kk) * N + c0 + cc;
            }
            *(float4*)(Bs + kk * BN + cc) = *(const float4*)src;
        }
        __syncthreads();
#pragma unroll
        for (int k = 0; k < BK; k++) {
            float4 b0 = *(const float4*)(Bs + k * BN + tx * 4);
            float4 b1 = *(const float4*)(Bs + k * BN + 64 + tx * 4);
            float a[TM];
#pragma unroll
            for (int rr = 0; rr < TM; rr++) {
                int row = (rr & 3) + ty * 4 + ((TM == 8) ? ((rr >> 2) * 64) : 0);
                a[rr] = As[row * 17 + k];
            }
#pragma unroll
            for (int rr = 0; rr < TM; rr++) {
                acc[rr][0] += a[rr] * b0.x;
                acc[rr][1] += a[rr] * b0.y;
                acc[rr][2] += a[rr] * b0.z;
                acc[rr][3] += a[rr] * b0.w;
                acc[rr][4] += a[rr] * b1.x;
                acc[rr][5] += a[rr] * b1.y;
                acc[rr][6] += a[rr] * b1.z;
                acc[rr][7] += a[rr] * b1.w;
            }
        }
        __syncthreads();
    }

    // ---- epilogues ----
    if constexpr (MODE == 1) {
        float4 bb0 = *(const float4*)(bias + c0 + tx * 4);
        float4 bb1 = *(const float4*)(bias + c0 + 64 + tx * 4);
        const int i0 = c0 >> 6;   // A row-block index (c0 multiple of 128 -> i0, i0+1)
#pragma unroll
        for (int rr = 0; rr < TM; rr++) {
            int t = t0 + (rr & 3) + ty * 4 + (rr >> 2) * 64;
            float s0 = g_expD[t * DST + i0];
            float s1 = g_expD[t * DST + i0 + 1];
            float4 v0 = make_float4((acc[rr][0] + bb0.x) * s0, (acc[rr][1] + bb0.y) * s0,
                                    (acc[rr][2] + bb0.z) * s0, (acc[rr][3] + bb0.w) * s0);
            float4 v1 = make_float4((acc[rr][4] + bb1.x) * s1, (acc[rr][5] + bb1.y) * s1,
                                    (acc[rr][6] + bb1.z) * s1, (acc[rr][7] + bb1.w) * s1);
            *(float4*)(g_A + (size_t)t * 4096 + c0 + tx * 4)      = v0;
            *(float4*)(g_A + (size_t)t * 4096 + c0 + 64 + tx * 4) = v1;
        }
    } else if constexpr (MODE == 2) {
        float4 bb0 = *(const float4*)(bias + c0 + tx * 4);
        float4 bb1 = *(const float4*)(bias + c0 + 64 + tx * 4);
        const int d0 = (c0 & 255) + tx * 4;
#pragma unroll
        for (int rr = 0; rr < TM; rr++) {
            int row = (rr & 3) + ty * 4 + (rr >> 2) * 64;
            int t = t0 + row;
            float4 x0 = *(const float4*)(X + t * DMOD + d0);
            float4 x1 = *(const float4*)(X + t * DMOD + d0 + 64);
            float p = (acc[rr][0] + bb0.x) * x0.x + (acc[rr][1] + bb0.y) * x0.y
                    + (acc[rr][2] + bb0.z) * x0.z + (acc[rr][3] + bb0.w) * x0.w
                    + (acc[rr][4] + bb1.x) * x1.x + (acc[rr][5] + bb1.y) * x1.y
                    + (acc[rr][6] + bb1.z) * x1.z + (acc[rr][7] + bb1.w) * x1.w;
            Red[row * 16 + tx] = p;
        }
        __syncthreads();
        if (tid < BM) {
            float s = 0.f;
#pragma unroll
            for (int q = 0; q < 16; q++) s += Red[tid * 16 + q];
            // [token][n*2 + p]: n = c0>>8, p = (c0>>7)&1
            g_BxPart[(t0 + tid) * 128 + ((c0 >> 8) << 1) + ((c0 >> 7) & 1)] = s;
        }
    } else {  // MODE 4: final output (bias already folded into K-extension)
#pragma unroll
        for (int rr = 0; rr < TM; rr++) {
            int t = t0 + (rr & 3) + ty * 4;
            *(float4*)(Out + (size_t)t * DMOD + c0 + tx * 4) =
                make_float4(acc[rr][0], acc[rr][1], acc[rr][2], acc[rr][3]);
            *(float4*)(Out + (size_t)t * DMOD + c0 + 64 + tx * 4) =
                make_float4(acc[rr][4], acc[rr][5], acc[rr][6], acc[rr][7]);
        }
    }
}

// ---------------- expD = exp(x@WD + bD), [4096 x 64] ----------------
__global__ __launch_bounds__(256) void expd_kernel(const float* __restrict__ X,
                                                   const float* __restrict__ WD,
                                                   const float* __restrict__ bD)
{
    __shared__ float xs[4][256];
    const int tid = threadIdx.x;
    const int t0  = blockIdx.x * 4;
    {
        int r = tid >> 6, c4 = (tid & 63) * 4;
        *(float4*)(&xs[r][c4]) = *(const float4*)(X + (t0 + r) * DMOD + c4);
    }
    __syncthreads();
    const int tt = tid >> 6;
    const int c  = tid & 63;
    float acc = bD[c];
#pragma unroll 8
    for (int k = 0; k < DMOD; k++) acc += xs[tt][k] * WD[k * DST + c];
    g_expD[(t0 + tt) * DST + c] = expf(acc);
}

// ---------------- sequential recurrence: h_t = A_t h_{t-1} + Bx_t ----------------
// One CTA per batch, 256 threads (i = tid&63 output row, g = tid>>6 quarter of j).
// Double-buffered smem staging of A_t, depth-2 register prefetch from L2-hot g_A.
__device__ __forceinline__ void scan_step(
    float4 (&r)[4], int t, const float* __restrict__ Abase,
    const float* __restrict__ BxPb, float* __restrict__ ghb,
    float (*Abuf)[64*68], float* hsm, float* psum,
    int tid, int i, int g)
{
    float* Ab_s = &Abuf[t & 1][0];
#pragma unroll
    for (int q = 0; q < 4; q++) {
        int idx4 = tid + 256 * q;
        int row = idx4 >> 4, w = idx4 & 15;
        *(float4*)(Ab_s + row * 68 + w * 4) = r[q];
    }
    __syncthreads();
    if (t + 2 < SEQ) {
        const float4* p = (const float4*)(Abase + (t + 2) * 4096);
#pragma unroll
        for (int q = 0; q < 4; q++) r[q] = p[tid + 256 * q];
    }
    float accv = 0.f;
    const float* arow = Ab_s + i * 68 + g * 16;
#pragma unroll
    for (int u = 0; u < 4; u++) {
        float4 a  = *(const float4*)(arow + u * 4);
        float4 h4 = *(const float4*)(hsm + g * 16 + u * 4);
        accv += a.x * h4.x + a.y * h4.y + a.z * h4.z + a.w * h4.w;
    }
    psum[i * 4 + g] = accv;
    __syncthreads();
    if (tid < 64) {
        float4 p4 = *(const float4*)(psum + tid * 4);
        float bx = BxPb[t * 128 + tid * 2] + BxPb[t * 128 + tid * 2 + 1];
        float hv = (p4.x + p4.y) + (p4.z + p4.w) + bx;
        hsm[tid] = hv;
        ghb[t * DST + tid] = hv;
    }
    // next step's post-staging barrier orders hsm for readers
}

__global__ __launch_bounds__(256) void scan_kernel()
{
    __shared__ float Abuf[2][64 * 68];
    __shared__ float hsm[64];
    __shared__ float psum[64 * 4];

    const int b   = blockIdx.x;
    const int tid = threadIdx.x;
    const int i   = tid & 63;
    const int g   = tid >> 6;

    const float* Abase = g_A + (size_t)b * SEQ * 4096;
    const float* BxPb  = g_BxPart + (size_t)b * SEQ * 128;
    float*       ghb   = g_h + (size_t)b * SEQ * DST;

    if (tid < 64) hsm[tid] = 0.f;

    float4 r0[4], r1[4];
    {
        const float4* p0 = (const float4*)(Abase);
        const float4* p1 = (const float4*)(Abase + 4096);
#pragma unroll
        for (int q = 0; q < 4; q++) { r0[q] = p0[tid + 256 * q]; r1[q] = p1[tid + 256 * q]; }
    }

    for (int t = 0; t < SEQ; t += 2) {
        scan_step(r0, t,     Abase, BxPb, ghb, Abuf, hsm, psum, tid, i, g);
        scan_step(r1, t + 1, Abase, BxPb, ghb, Abuf, hsm, psum, tid, i, g);
    }
}

// ---------------- launch ----------------
extern "C" void kernel_launch(void* const* d_in, const int* in_sizes, int n_in,
                              void* d_out, int out_size)
{
    const float* x  = (const float*)d_in[0];
    const float* WA = (const float*)d_in[1];
    const float* bA = (const float*)d_in[2];
    const float* WB = (const float*)d_in[3];
    const float* bB = (const float*)d_in[4];
    const float* WC = (const float*)d_in[5];
    const float* bC = (const float*)d_in[6];
    const float* WD = (const float*)d_in[7];
    const float* bD = (const float*)d_in[8];
    // d_in[9]/d_in[10] (Wdelta, bdelta): reference computes-then-discards delta -> skipped.
    float* out = (float*)d_out;

    dim3 blk(256);

    // 1) expD (needed by A epilogue)
    expd_kernel<<<NTOK / 4, blk>>>(x, WD, bD);
    // 2) Bx partials fused into WB-GEMM epilogue (Bm never materialized)
    gemm_kernel<2, 16384, 8><<<dim3(128, 32), blk>>>(x, WB, bB, nullptr);
    // 3) A = (x@WA + bA)*expD — last big write, stays L2-resident for the scan
    gemm_kernel<1, 4096, 8><<<dim3(32, 32), blk>>>(x, WA, bA, nullptr);
    // 4) sequential recurrence (4 CTAs, one per batch); folds Bx partial sum
    scan_kernel<<<BATCH, blk>>>();
    // 5) out = (h (x) x) @ WCr + h@bC  — Cm never materialized
    gemm_kernel<4, 256, 4><<<dim3(2, 64), blk>>>(x, WC, bC, out);
}

// round 3
// speedup vs baseline: 1.2258x; 1.2258x over previous
#include <cuda_runtime.h>
#include <math.h>

#define BATCH 4
#define SEQ   1024
#define DMOD  256
#define DST   64
#define NTOK  (BATCH*SEQ)     // 4096 tokens
#define CHUNK 32
#define NCHUNK (NTOK/CHUNK)   // 128 chunks (32 per batch)

// ---------------- scratch (static __device__ — no allocs allowed) ----------------
__device__ float g_A[NTOK * DST * DST];     // 64 MB: exp(logD)-scaled A, [token][i*64+j]
__device__ float g_expD[NTOK * DST];        // exp(x@WD + bD)
__device__ float g_BxPart[NTOK * DST * 2];  // partial Bx, [token][n*2+p]
__device__ float g_h[NTOK * DST];           // recurrence states, [token][n]
__device__ float g_M[NCHUNK * DST * DST];   // 2 MB: chunk transition matrices [chunk][i*64+k]
__device__ float g_v[NCHUNK * DST];         // chunk offset vectors
__device__ float g_s[NCHUNK * DST];         // chunk entry states

// ---------------- GEMM template (unchanged from R2 — at fp32 peak) ----------------
// MODE 1: g_A = (X@WA + bA) * expD          (N = 4096,  TM = 8)
// MODE 2: Bx partials from (X@WB + bB)      (N = 16384, TM = 8; Bm never stored)
// MODE 4: out = Y@WCr (+ h@bC fold)         (virtual K = 16448, TM = 4)
template<int MODE, int N, int TM>
__global__ __launch_bounds__(256)
void gemm_kernel(const float* __restrict__ X, const float* __restrict__ W,
                 const float* __restrict__ bias, float* __restrict__ Out)
{
    constexpr int BM = TM * 16;
    constexpr int BK = 16;
    constexpr int BN = 128;
    __shared__ float As[BM * 17];
    __shared__ float Bs[BK * BN];
    __shared__ float Red[(MODE == 2) ? BM * 16 : 1];

    const int tid = threadIdx.x;
    const int t0  = blockIdx.y * BM;
    const int c0  = blockIdx.x * BN;
    const int tx  = tid & 15;
    const int ty  = tid >> 4;

    float acc[TM][8];
#pragma unroll
    for (int i = 0; i < TM; i++)
#pragma unroll
        for (int j = 0; j < 8; j++) acc[i][j] = 0.f;

    constexpr int KTOT = (MODE == 4) ? (16384 + 64) : DMOD;

    for (int k0 = 0; k0 < KTOT; k0 += BK) {
        if constexpr (MODE == 4) {
            int m = tid >> 2, kq = tid & 3;
            float4 v;
            if (k0 < 16384) {
                float hv  = g_h[(t0 + m) * DST + (k0 >> 8)];
                float4 xv = *(const float4*)(X + (t0 + m) * DMOD + (k0 & 255) + kq * 4);
                v = make_float4(hv * xv.x, hv * xv.y, hv * xv.z, hv * xv.w);
            } else {
                v = *(const float4*)(g_h + (t0 + m) * DST + (k0 - 16384) + kq * 4);
            }
            float* a = As + m * 17 + kq * 4;
            a[0] = v.x; a[1] = v.y; a[2] = v.z; a[3] = v.w;
        } else {
#pragma unroll
            for (int q = 0; q < 2; q++) {
                int idx = tid + 256 * q;
                int m = idx >> 2, kq = idx & 3;
                float4 v = *(const float4*)(X + (t0 + m) * DMOD + k0 + kq * 4);
                float* a = As + m * 17 + kq * 4;
                a[0] = v.x; a[1] = v.y; a[2] = v.z; a[3] = v.w;
            }
        }
#pragma unroll
        for (int q = 0; q < 2; q++) {
            int idx = tid + 256 * q;
            int kk = idx >> 5, cc = (idx & 31) * 4;
            const float* src;
            if constexpr (MODE == 4) {
                if (k0 < 16384)
                    src = W + (size_t)((k0 & 255) + kk) * 16384 + (k0 >> 8) * 256 + c0 + cc;
                else
                    src = bias + (size_t)(k0 - 16384 + kk) * 256 + c0 + cc;
            } else {
                src = W + (size_t)(k0 + kk) * N + c0 + cc;
            }
            *(float4*)(Bs + kk * BN + cc) = *(const float4*)src;
        }
        __syncthreads();
#pragma unroll
        for (int k = 0; k < BK; k++) {
            float4 b0 = *(const float4*)(Bs + k * BN + tx * 4);
            float4 b1 = *(const float4*)(Bs + k * BN + 64 + tx * 4);
            float a[TM];
#pragma unroll
            for (int rr = 0; rr < TM; rr++) {
                int row = (rr & 3) + ty * 4 + ((TM == 8) ? ((rr >> 2) * 64) : 0);
                a[rr] = As[row * 17 + k];
            }
#pragma unroll
            for (int rr = 0; rr < TM; rr++) {
                acc[rr][0] += a[rr] * b0.x;
                acc[rr][1] += a[rr] * b0.y;
                acc[rr][2] += a[rr] * b0.z;
                acc[rr][3] += a[rr] * b0.w;
                acc[rr][4] += a[rr] * b1.x;
                acc[rr][5] += a[rr] * b1.y;
                acc[rr][6] += a[rr] * b1.z;
                acc[rr][7] += a[rr] * b1.w;
            }
        }
        __syncthreads();
    }

    if constexpr (MODE == 1) {
        float4 bb0 = *(const float4*)(bias + c0 + tx * 4);
        float4 bb1 = *(const float4*)(bias + c0 + 64 + tx * 4);
        const int i0 = c0 >> 6;
#pragma unroll
        for (int rr = 0; rr < TM; rr++) {
            int t = t0 + (rr & 3) + ty * 4 + (rr >> 2) * 64;
            float s0 = g_expD[t * DST + i0];
            float s1 = g_expD[t * DST + i0 + 1];
            float4 v0 = make_float4((acc[rr][0] + bb0.x) * s0, (acc[rr][1] + bb0.y) * s0,
                                    (acc[rr][2] + bb0.z) * s0, (acc[rr][3] + bb0.w) * s0);
            float4 v1 = make_float4((acc[rr][4] + bb1.x) * s1, (acc[rr][5] + bb1.y) * s1,
                                    (acc[rr][6] + bb1.z) * s1, (acc[rr][7] + bb1.w) * s1);
            *(float4*)(g_A + (size_t)t * 4096 + c0 + tx * 4)      = v0;
            *(float4*)(g_A + (size_t)t * 4096 + c0 + 64 + tx * 4) = v1;
        }
    } else if constexpr (MODE == 2) {
        float4 bb0 = *(const float4*)(bias + c0 + tx * 4);
        float4 bb1 = *(const float4*)(bias + c0 + 64 + tx * 4);
        const int d0 = (c0 & 255) + tx * 4;
#pragma unroll
        for (int rr = 0; rr < TM; rr++) {
            int row = (rr & 3) + ty * 4 + (rr >> 2) * 64;
            int t = t0 + row;
            float4 x0 = *(const float4*)(X + t * DMOD + d0);
            float4 x1 = *(const float4*)(X + t * DMOD + d0 + 64);
            float p = (acc[rr][0] + bb0.x) * x0.x + (acc[rr][1] + bb0.y) * x0.y
                    + (acc[rr][2] + bb0.z) * x0.z + (acc[rr][3] + bb0.w) * x0.w
                    + (acc[rr][4] + bb1.x) * x1.x + (acc[rr][5] + bb1.y) * x1.y
                    + (acc[rr][6] + bb1.z) * x1.z + (acc[rr][7] + bb1.w) * x1.w;
            Red[row * 16 + tx] = p;
        }
        __syncthreads();
        if (tid < BM) {
            float s = 0.f;
#pragma unroll
            for (int q = 0; q < 16; q++) s += Red[tid * 16 + q];
            g_BxPart[(t0 + tid) * 128 + ((c0 >> 8) << 1) + ((c0 >> 7) & 1)] = s;
        }
    } else {
#pragma unroll
        for (int rr = 0; rr < TM; rr++) {
            int t = t0 + (rr & 3) + ty * 4;
            *(float4*)(Out + (size_t)t * DMOD + c0 + tx * 4) =
                make_float4(acc[rr][0], acc[rr][1], acc[rr][2], acc[rr][3]);
            *(float4*)(Out + (size_t)t * DMOD + c0 + 64 + tx * 4) =
                make_float4(acc[rr][4], acc[rr][5], acc[rr][6], acc[rr][7]);
        }
    }
}

// ---------------- expD = exp(x@WD + bD) ----------------
__global__ __launch_bounds__(256) void expd_kernel(const float* __restrict__ X,
                                                   const float* __restrict__ WD,
                                                   const float* __restrict__ bD)
{
    __shared__ float xs[4][256];
    const int tid = threadIdx.x;
    const int t0  = blockIdx.x * 4;
    {
        int r = tid >> 6, c4 = (tid & 63) * 4;
        *(float4*)(&xs[r][c4]) = *(const float4*)(X + (t0 + r) * DMOD + c4);
    }
    __syncthreads();
    const int tt = tid >> 6;
    const int c  = tid & 63;
    float acc = bD[c];
#pragma unroll 8
    for (int k = 0; k < DMOD; k++) acc += xs[tt][k] * WD[k * DST + c];
    g_expD[(t0 + tt) * DST + c] = expf(acc);
}

// ================= Phase A: per-chunk transition matrices =================
// 128 CTAs (one per 32-token chunk). Computes M_c = A_{31}...A_0 and
// v_c = sum_t (prod_{s>t} A_s) b_t via 31 sequential 64x64x64 smem matmuls.
// 256 threads: 4x4 register tile per thread (16x16 grid covers 64x64).
// A_t staged non-transposed [i][68]; scalar a-loads broadcast-dedup across warp.
__global__ __launch_bounds__(256) void scanA_kernel()
{
    extern __shared__ float sm[];
    float* As0 = sm;
    float* As1 = sm + 64 * 68;
    float* Ms0 = sm + 2 * 64 * 68;
    float* Ms1 = sm + 3 * 64 * 68;   // cols 0..63 = M, col 64 = v

    const int chunk  = blockIdx.x;
    const int tid    = threadIdx.x;
    const int token0 = chunk * CHUNK;
    const float* Ab  = g_A + (size_t)token0 * 4096;
    const float* Bxb = g_BxPart + (size_t)token0 * 128;

    const int i0 = (tid >> 4) * 4;
    const int j0 = (tid & 15) * 4;

    // init: M = A_0 (row-major into Ms0), v = b_0
#pragma unroll
    for (int q = 0; q < 4; q++) {
        int o = (tid + 256 * q) * 4;
        *(float4*)(Ms0 + (o >> 6) * 68 + (o & 63)) = *(const float4*)(Ab + o);
    }
    if (tid < 64) Ms0[tid * 68 + 64] = Bxb[tid * 2] + Bxb[tid * 2 + 1];

    // prefetch A_1
    float4 r[4];
#pragma unroll
    for (int q = 0; q < 4; q++) r[q] = *(const float4*)(Ab + 4096 + (tid + 256 * q) * 4);

    for (int t = 1; t < CHUNK; t++) {
        float* Asb        = (t & 1) ? As1 : As0;
        const float* Mcur = ((t - 1) & 1) ? Ms1 : Ms0;
        float* Mnxt       = (t & 1) ? Ms1 : Ms0;

        // stage A_t
#pragma unroll
        for (int q = 0; q < 4; q++) {
            int o = (tid + 256 * q) * 4;
            *(float4*)(Asb + (o >> 6) * 68 + (o & 63)) = r[q];
        }
        __syncthreads();
        // prefetch A_{t+1}
        if (t + 1 < CHUNK) {
#pragma unroll
            for (int q = 0; q < 4; q++)
                r[q] = *(const float4*)(Ab + (size_t)(t + 1) * 4096 + (tid + 256 * q) * 4);
        }

        // newM[i0..i0+3][j0..j0+3] = A_t * M
        float acc[4][4];
#pragma unroll
        for (int ii = 0; ii < 4; ii++)
#pragma unroll
            for (int jj = 0; jj < 4; jj++) acc[ii][jj] = 0.f;

#pragma unroll 4
        for (int k = 0; k < 64; k++) {
            float4 m4 = *(const float4*)(Mcur + k * 68 + j0);
            float a0 = Asb[(i0 + 0) * 68 + k];
            float a1 = Asb[(i0 + 1) * 68 + k];
            float a2 = Asb[(i0 + 2) * 68 + k];
            float a3 = Asb[(i0 + 3) * 68 + k];
            acc[0][0] += a0 * m4.x; acc[0][1] += a0 * m4.y; acc[0][2] += a0 * m4.z; acc[0][3] += a0 * m4.w;
            acc[1][0] += a1 * m4.x; acc[1][1] += a1 * m4.y; acc[1][2] += a1 * m4.z; acc[1][3] += a1 * m4.w;
            acc[2][0] += a2 * m4.x; acc[2][1] += a2 * m4.y; acc[2][2] += a2 * m4.z; acc[2][3] += a2 * m4.w;
            acc[3][0] += a3 * m4.x; acc[3][1] += a3 * m4.y; acc[3][2] += a3 * m4.z; acc[3][3] += a3 * m4.w;
        }

        // v update (64 threads): vnew[i] = A_t[i,:] . v + b_t[i]
        float vnew = 0.f;
        if (tid < 64) {
            vnew = Bxb[t * 128 + tid * 2] + Bxb[t * 128 + tid * 2 + 1];
#pragma unroll 4
            for (int k = 0; k < 64; k++)
                vnew += Asb[tid * 68 + k] * Mcur[k * 68 + 64];
        }

#pragma unroll
        for (int ii = 0; ii < 4; ii++)
            *(float4*)(Mnxt + (i0 + ii) * 68 + j0) =
                make_float4(acc[ii][0], acc[ii][1], acc[ii][2], acc[ii][3]);
        if (tid < 64) Mnxt[tid * 68 + 64] = vnew;
        // next iteration's stage-barrier orders Mnxt for its readers
    }

    __syncthreads();
    const float* Mf = Ms1;   // (CHUNK-1)&1 == 1
#pragma unroll
    for (int q = 0; q < 4; q++) {
        int o = (tid + 256 * q) * 4;
        *(float4*)(g_M + (size_t)chunk * 4096 + o) = *(const float4*)(Mf + (o >> 6) * 68 + (o & 63));
    }
    if (tid < 64) g_v[chunk * 64 + tid] = Mf[tid * 68 + 64];
}

// ================= Phase B: combine chunks (4 CTAs, 32 sequential steps) =================
__device__ __forceinline__ void bstep(
    float4 (&r)[4], int c, const float* __restrict__ Mbase,
    const float* __restrict__ vb, float* __restrict__ sb,
    float (*Mb)[64 * 68], float* hsm, float* psum, int tid, int i, int g)
{
    float* Ms_ = &Mb[c & 1][0];
#pragma unroll
    for (int q = 0; q < 4; q++) {
        int idx4 = tid + 256 * q;
        *(float4*)(Ms_ + (idx4 >> 4) * 68 + (idx4 & 15) * 4) = r[q];
    }
    __syncthreads();
    if (c + 2 < 32) {
        const float4* p = (const float4*)(Mbase + (size_t)(c + 2) * 4096);
#pragma unroll
        for (int q = 0; q < 4; q++) r[q] = p[tid + 256 * q];
    }
    if (tid < 64) sb[c * 64 + tid] = hsm[tid];   // state BEFORE chunk c
    float accv = 0.f;
    const float* mrow = Ms_ + i * 68 + g * 16;
#pragma unroll
    for (int u = 0; u < 4; u++) {
        float4 a  = *(const float4*)(mrow + u * 4);
        float4 h4 = *(const float4*)(hsm + g * 16 + u * 4);
        accv += a.x * h4.x + a.y * h4.y + a.z * h4.z + a.w * h4.w;
    }
    psum[i * 4 + g] = accv;
    __syncthreads();
    if (tid < 64) {
        float4 p4 = *(const float4*)(psum + tid * 4);
        hsm[tid] = (p4.x + p4.y) + (p4.z + p4.w) + vb[c * 64 + tid];
    }
}

__global__ __launch_bounds__(256) void scanB_kernel()
{
    __shared__ float Mb[2][64 * 68];
    __shared__ float hsm[64];
    __shared__ float psum[256];
    const int b = blockIdx.x, tid = threadIdx.x;
    const int i = tid & 63, g = tid >> 6;
    const float* Mbase = g_M + (size_t)b * 32 * 4096;
    const float* vb    = g_v + b * 32 * 64;
    float*       sb    = g_s + b * 32 * 64;
    if (tid < 64) hsm[tid] = 0.f;
    float4 r0[4], r1[4];
    {
        const float4* p0 = (const float4*)(Mbase);
        const float4* p1 = (const float4*)(Mbase + 4096);
#pragma unroll
        for (int q = 0; q < 4; q++) { r0[q] = p0[tid + 256 * q]; r1[q] = p1[tid + 256 * q]; }
    }
    for (int c = 0; c < 32; c += 2) {
        bstep(r0, c,     Mbase, vb, sb, Mb, hsm, psum, tid, i, g);
        bstep(r1, c + 1, Mbase, vb, sb, Mb, hsm, psum, tid, i, g);
    }
}

// ================= Phase C: within-chunk recurrence (128 CTAs x 32 steps) =================
__device__ __forceinline__ void cstep(
    float4 (&r)[4], int t, const float* __restrict__ Abase,
    const float* __restrict__ BxPb, float* __restrict__ ghb,
    float (*Abuf)[64 * 68], float* hsm, float* psum, int tid, int i, int g)
{
    float* Ab_s = &Abuf[t & 1][0];
#pragma unroll
    for (int q = 0; q < 4; q++) {
        int idx4 = tid + 256 * q;
        *(float4*)(Ab_s + (idx4 >> 4) * 68 + (idx4 & 15) * 4) = r[q];
    }
    __syncthreads();
    if (t + 2 < CHUNK) {
        const float4* p = (const float4*)(Abase + (size_t)(t + 2) * 4096);
#pragma unroll
        for (int q = 0; q < 4; q++) r[q] = p[tid + 256 * q];
    }
    float accv = 0.f;
    const float* arow = Ab_s + i * 68 + g * 16;
#pragma unroll
    for (int u = 0; u < 4; u++) {
        float4 a  = *(const float4*)(arow + u * 4);
        float4 h4 = *(const float4*)(hsm + g * 16 + u * 4);
        accv += a.x * h4.x + a.y * h4.y + a.z * h4.z + a.w * h4.w;
    }
    psum[i * 4 + g] = accv;
    __syncthreads();
    if (tid < 64) {
        float4 p4 = *(const float4*)(psum + tid * 4);
        float bx = BxPb[t * 128 + tid * 2] + BxPb[t * 128 + tid * 2 + 1];
        float hv = (p4.x + p4.y) + (p4.z + p4.w) + bx;
        hsm[tid] = hv;
        ghb[t * DST + tid] = hv;
    }
}

__global__ __launch_bounds__(256) void scanC_kernel()
{
    __shared__ float Abuf[2][64 * 68];
    __shared__ float hsm[64];
    __shared__ float psum[256];
    const int chunk = blockIdx.x, tid = threadIdx.x;
    const int i = tid & 63, g = tid >> 6;
    const int token0 = chunk * CHUNK;
    const float* Abase = g_A + (size_t)token0 * 4096;
    const float* BxPb  = g_BxPart + (size_t)token0 * 128;
    float*       ghb   = g_h + (size_t)token0 * DST;

    if (tid < 64) hsm[tid] = g_s[chunk * 64 + tid];

    float4 r0[4], r1[4];
    {
        const float4* p0 = (const float4*)(Abase);
        const float4* p1 = (const float4*)(Abase + 4096);
#pragma unroll
        for (int q = 0; q < 4; q++) { r0[q] = p0[tid + 256 * q]; r1[q] = p1[tid + 256 * q]; }
    }
    for (int t = 0; t < CHUNK; t += 2) {
        cstep(r0, t,     Abase, BxPb, ghb, Abuf, hsm, psum, tid, i, g);
        cstep(r1, t + 1, Abase, BxPb, ghb, Abuf, hsm, psum, tid, i, g);
    }
}

// ---------------- launch ----------------
extern "C" void kernel_launch(void* const* d_in, const int* in_sizes, int n_in,
                              void* d_out, int out_size)
{
    const float* x  = (const float*)d_in[0];
    const float* WA = (const float*)d_in[1];
    const float* bA = (const float*)d_in[2];
    const float* WB = (const float*)d_in[3];
    const float* bB = (const float*)d_in[4];
    const float* WC = (const float*)d_in[5];
    const float* bC = (const float*)d_in[6];
    const float* WD = (const float*)d_in[7];
    const float* bD = (const float*)d_in[8];
    // d_in[9]/d_in[10] (Wdelta, bdelta): reference computes-then-discards delta -> skipped.
    float* out = (float*)d_out;

    dim3 blk(256);
    const int scanA_smem = 4 * 64 * 68 * (int)sizeof(float);   // 69632 B > 48KB static limit
    cudaFuncSetAttribute(scanA_kernel, cudaFuncAttributeMaxDynamicSharedMemorySize, scanA_smem);

    // 1) expD (needed by A epilogue)
    expd_kernel<<<NTOK / 4, blk>>>(x, WD, bD);
    // 2) Bx partials fused into WB-GEMM epilogue (Bm never materialized)
    gemm_kernel<2, 16384, 8><<<dim3(128, 32), blk>>>(x, WB, bB, nullptr);
    // 3) A = (x@WA + bA)*expD
    gemm_kernel<1, 4096, 8><<<dim3(32, 32), blk>>>(x, WA, bA, nullptr);
    // 4) chunked scan: A (chunk matrices) -> B (combine) -> C (within-chunk states)
    scanA_kernel<<<NCHUNK, blk, scanA_smem>>>();
    scanB_kernel<<<BATCH, blk>>>();
    scanC_kernel<<<NCHUNK, blk>>>();
    // 5) out = (h (x) x) @ WCr + h@bC  — Cm never materialized
    gemm_kernel<4, 256, 4><<<dim3(2, 64), blk>>>(x, WC, bC, out);
}

// round 4
// speedup vs baseline: 1.3075x; 1.0667x over previous
#include <cuda_runtime.h>
#include <math.h>

#define BATCH 4
#define SEQ   1024
#define DMOD  256
#define DST   64
#define NTOK  (BATCH*SEQ)     // 4096 tokens
#define CHUNK 32
#define NCHUNK (NTOK/CHUNK)   // 128 chunks (32 per batch)

typedef unsigned long long ull;

// ---------------- f32x2 packed-FMA helpers (Blackwell FFMA2 via PTX) ----------------
__device__ __forceinline__ ull pack2(float lo, float hi) {
    ull r; asm("mov.b64 %0, {%1,%2};" : "=l"(r) : "f"(lo), "f"(hi)); return r;
}
__device__ __forceinline__ void unpack2(ull v, float& lo, float& hi) {
    asm("mov.b64 {%0,%1}, %2;" : "=f"(lo), "=f"(hi) : "l"(v));
}
__device__ __forceinline__ ull fma2(ull a, ull b, ull c) {
    ull d; asm("fma.rn.f32x2 %0, %1, %2, %3;" : "=l"(d) : "l"(a), "l"(b), "l"(c)); return d;
}

// ---------------- scratch (static __device__ — no allocs allowed) ----------------
__device__ float g_A[NTOK * DST * DST];     // 64 MB: exp(logD)-scaled A, [token][i*64+j]
__device__ float g_expD[NTOK * DST];        // exp(x@WD + bD)
__device__ float g_BxPart[NTOK * DST * 2];  // partial Bx, [token][n*2+p]
__device__ float g_h[NTOK * DST];           // recurrence states, [token][n]
__device__ float g_M[NCHUNK * DST * DST];   // 2 MB: chunk transition matrices
__device__ float g_v[NCHUNK * DST];         // chunk offset vectors
__device__ float g_s[NCHUNK * DST];         // chunk entry states

// ---------------- GEMM template (f32x2 inner loop) ----------------
// MODE 1: g_A = (X@WA + bA) * expD          (N = 4096,  TM = 8)
// MODE 2: Bx partials from (X@WB + bB)      (N = 16384, TM = 8; Bm never stored)
// MODE 4: out = Y@WCr (+ h@bC fold)         (virtual K = 16448, TM = 4)
// As is stored k-major [k][m] (pad) so row-pairs load as packed LDS.64 operands.
template<int MODE, int N, int TM>
__global__ __launch_bounds__(256)
void gemm_kernel(const float* __restrict__ X, const float* __restrict__ W,
                 const float* __restrict__ bias, float* __restrict__ Out)
{
    constexpr int BM   = TM * 16;
    constexpr int BK   = 16;
    constexpr int BN   = 128;
    constexpr int ASTR = BM + 2;            // 130 / 66: keeps 8B alignment + bank spread
    __shared__ float As[BK * ASTR];         // [k][m]
    __shared__ float Bs[BK * BN];           // [k][n]
    __shared__ float Red[(MODE == 2) ? BM * 16 : 1];

    const int tid = threadIdx.x;
    const int t0  = blockIdx.y * BM;
    const int c0  = blockIdx.x * BN;
    const int tx  = tid & 15;
    const int ty  = tid >> 4;

    constexpr int NP = TM / 2;              // row-pairs per thread
    ull acc2[NP][8];
#pragma unroll
    for (int p = 0; p < NP; p++)
#pragma unroll
        for (int j = 0; j < 8; j++) acc2[p][j] = 0ull;

    constexpr int KTOT = (MODE == 4) ? (16384 + 64) : DMOD;

    for (int k0 = 0; k0 < KTOT; k0 += BK) {
        // ---- A tile: load [m][4k] float4, store transposed k-major ----
        if constexpr (MODE == 4) {
            int m = tid >> 2, kq = tid & 3;
            float4 v;
            if (k0 < 16384) {
                float hv  = g_h[(t0 + m) * DST + (k0 >> 8)];
                float4 xv = *(const float4*)(X + (t0 + m) * DMOD + (k0 & 255) + kq * 4);
                v = make_float4(hv * xv.x, hv * xv.y, hv * xv.z, hv * xv.w);
            } else {
                v = *(const float4*)(g_h + (t0 + m) * DST + (k0 - 16384) + kq * 4);
            }
            As[(kq * 4 + 0) * ASTR + m] = v.x;
            As[(kq * 4 + 1) * ASTR + m] = v.y;
            As[(kq * 4 + 2) * ASTR + m] = v.z;
            As[(kq * 4 + 3) * ASTR + m] = v.w;
        } else {
#pragma unroll
            for (int q = 0; q < 2; q++) {
                int idx = tid + 256 * q;
                int m = idx >> 2, kq = idx & 3;
                float4 v = *(const float4*)(X + (t0 + m) * DMOD + k0 + kq * 4);
                As[(kq * 4 + 0) * ASTR + m] = v.x;
                As[(kq * 4 + 1) * ASTR + m] = v.y;
                As[(kq * 4 + 2) * ASTR + m] = v.z;
                As[(kq * 4 + 3) * ASTR + m] = v.w;
            }
        }
        // ---- B tile ----
#pragma unroll
        for (int q = 0; q < 2; q++) {
            int idx = tid + 256 * q;
            int kk = idx >> 5, cc = (idx & 31) * 4;
            const float* src;
            if constexpr (MODE == 4) {
                if (k0 < 16384)
                    src = W + (size_t)((k0 & 255) + kk) * 16384 + (k0 >> 8) * 256 + c0 + cc;
                else
                    src = bias + (size_t)(k0 - 16384 + kk) * 256 + c0 + cc;
            } else {
                src = W + (size_t)(k0 + kk) * N + c0 + cc;
            }
            *(float4*)(Bs + kk * BN + cc) = *(const float4*)src;
        }
        __syncthreads();

#pragma unroll
        for (int k = 0; k < BK; k++) {
            const float* Ak = As + k * ASTR;
            ull a[NP];
            a[0] = *(const ull*)(Ak + ty * 4);          // rows ty*4, ty*4+1
            a[1] = *(const ull*)(Ak + ty * 4 + 2);      // rows ty*4+2, +3
            if constexpr (TM == 8) {
                a[2] = *(const ull*)(Ak + 64 + ty * 4);
                a[3] = *(const ull*)(Ak + 64 + ty * 4 + 2);
            }
            float4 b0 = *(const float4*)(Bs + k * BN + tx * 4);
            float4 b1 = *(const float4*)(Bs + k * BN + 64 + tx * 4);
            ull bb[8];
            bb[0] = pack2(b0.x, b0.x); bb[1] = pack2(b0.y, b0.y);
            bb[2] = pack2(b0.z, b0.z); bb[3] = pack2(b0.w, b0.w);
            bb[4] = pack2(b1.x, b1.x); bb[5] = pack2(b1.y, b1.y);
            bb[6] = pack2(b1.z, b1.z); bb[7] = pack2(b1.w, b1.w);
#pragma unroll
            for (int p = 0; p < NP; p++)
#pragma unroll
                for (int j = 0; j < 8; j++)
                    acc2[p][j] = fma2(a[p], bb[j], acc2[p][j]);
        }
        __syncthreads();
    }

    // ---- unpack to classic layout: row = (rr&3)+ty*4+(rr>>2)*64 ----
    float acc[TM][8];
#pragma unroll
    for (int p = 0; p < NP; p++)
#pragma unroll
        for (int j = 0; j < 8; j++) {
            float lo, hi;
            unpack2(acc2[p][j], lo, hi);
            int rr = ((p >> 1) << 2) + (p & 1) * 2;
            acc[rr][j]     = lo;
            acc[rr + 1][j] = hi;
        }

    // ---- epilogues ----
    if constexpr (MODE == 1) {
        float4 bb0 = *(const float4*)(bias + c0 + tx * 4);
        float4 bb1 = *(const float4*)(bias + c0 + 64 + tx * 4);
        const int i0 = c0 >> 6;
#pragma unroll
        for (int rr = 0; rr < TM; rr++) {
            int t = t0 + (rr & 3) + ty * 4 + (rr >> 2) * 64;
            float s0 = g_expD[t * DST + i0];
            float s1 = g_expD[t * DST + i0 + 1];
            float4 v0 = make_float4((acc[rr][0] + bb0.x) * s0, (acc[rr][1] + bb0.y) * s0,
                                    (acc[rr][2] + bb0.z) * s0, (acc[rr][3] + bb0.w) * s0);
            float4 v1 = make_float4((acc[rr][4] + bb1.x) * s1, (acc[rr][5] + bb1.y) * s1,
                                    (acc[rr][6] + bb1.z) * s1, (acc[rr][7] + bb1.w) * s1);
            *(float4*)(g_A + (size_t)t * 4096 + c0 + tx * 4)      = v0;
            *(float4*)(g_A + (size_t)t * 4096 + c0 + 64 + tx * 4) = v1;
        }
    } else if constexpr (MODE == 2) {
        float4 bb0 = *(const float4*)(bias + c0 + tx * 4);
        float4 bb1 = *(const float4*)(bias + c0 + 64 + tx * 4);
        const int d0 = (c0 & 255) + tx * 4;
#pragma unroll
        for (int rr = 0; rr < TM; rr++) {
            int row = (rr & 3) + ty * 4 + (rr >> 2) * 64;
            int t = t0 + row;
            float4 x0 = *(const float4*)(X + t * DMOD + d0);
            float4 x1 = *(const float4*)(X + t * DMOD + d0 + 64);
            float p = (acc[rr][0] + bb0.x) * x0.x + (acc[rr][1] + bb0.y) * x0.y
                    + (acc[rr][2] + bb0.z) * x0.z + (acc[rr][3] + bb0.w) * x0.w
                    + (acc[rr][4] + bb1.x) * x1.x + (acc[rr][5] + bb1.y) * x1.y
                    + (acc[rr][6] + bb1.z) * x1.z + (acc[rr][7] + bb1.w) * x1.w;
            Red[row * 16 + tx] = p;
        }
        __syncthreads();
        if (tid < BM) {
            float s = 0.f;
#pragma unroll
            for (int q = 0; q < 16; q++) s += Red[tid * 16 + q];
            g_BxPart[(t0 + tid) * 128 + ((c0 >> 8) << 1) + ((c0 >> 7) & 1)] = s;
        }
    } else {
#pragma unroll
        for (int rr = 0; rr < TM; rr++) {
            int t = t0 + (rr & 3) + ty * 4;
            *(float4*)(Out + (size_t)t * DMOD + c0 + tx * 4) =
                make_float4(acc[rr][0], acc[rr][1], acc[rr][2], acc[rr][3]);
            *(float4*)(Out + (size_t)t * DMOD + c0 + 64 + tx * 4) =
                make_float4(acc[rr][4], acc[rr][5], acc[rr][6], acc[rr][7]);
        }
    }
}

// ---------------- expD = exp(x@WD + bD) ----------------
__global__ __launch_bounds__(256) void expd_kernel(const float* __restrict__ X,
                                                   const float* __restrict__ WD,
                                                   const float* __restrict__ bD)
{
    __shared__ float xs[4][256];
    const int tid = threadIdx.x;
    const int t0  = blockIdx.x * 4;
    {
        int r = tid >> 6, c4 = (tid & 63) * 4;
        *(float4*)(&xs[r][c4]) = *(const float4*)(X + (t0 + r) * DMOD + c4);
    }
    __syncthreads();
    const int tt = tid >> 6;
    const int c  = tid & 63;
    float acc = bD[c];
#pragma unroll 8
    for (int k = 0; k < DMOD; k++) acc += xs[tt][k] * WD[k * DST + c];
    g_expD[(t0 + tt) * DST + c] = expf(acc);
}

// ================= Phase A: per-chunk transition matrices =================
__global__ __launch_bounds__(256) void scanA_kernel()
{
    extern __shared__ float sm[];
    float* As0 = sm;
    float* As1 = sm + 64 * 68;
    float* Ms0 = sm + 2 * 64 * 68;
    float* Ms1 = sm + 3 * 64 * 68;   // cols 0..63 = M, col 64 = v

    const int chunk  = blockIdx.x;
    const int tid    = threadIdx.x;
    const int token0 = chunk * CHUNK;
    const float* Ab  = g_A + (size_t)token0 * 4096;
    const float* Bxb = g_BxPart + (size_t)token0 * 128;

    const int i0 = (tid >> 4) * 4;
    const int j0 = (tid & 15) * 4;

#pragma unroll
    for (int q = 0; q < 4; q++) {
        int o = (tid + 256 * q) * 4;
        *(float4*)(Ms0 + (o >> 6) * 68 + (o & 63)) = *(const float4*)(Ab + o);
    }
    if (tid < 64) Ms0[tid * 68 + 64] = Bxb[tid * 2] + Bxb[tid * 2 + 1];

    float4 r[4];
#pragma unroll
    for (int q = 0; q < 4; q++) r[q] = *(const float4*)(Ab + 4096 + (tid + 256 * q) * 4);

    for (int t = 1; t < CHUNK; t++) {
        float* Asb        = (t & 1) ? As1 : As0;
        const float* Mcur = ((t - 1) & 1) ? Ms1 : Ms0;
        float* Mnxt       = (t & 1) ? Ms1 : Ms0;

#pragma unroll
        for (int q = 0; q < 4; q++) {
            int o = (tid + 256 * q) * 4;
            *(float4*)(Asb + (o >> 6) * 68 + (o & 63)) = r[q];
        }
        __syncthreads();
        if (t + 1 < CHUNK) {
#pragma unroll
            for (int q = 0; q < 4; q++)
                r[q] = *(const float4*)(Ab + (size_t)(t + 1) * 4096 + (tid + 256 * q) * 4);
        }

        float acc[4][4];
#pragma unroll
        for (int ii = 0; ii < 4; ii++)
#pragma unroll
            for (int jj = 0; jj < 4; jj++) acc[ii][jj] = 0.f;

#pragma unroll 4
        for (int k = 0; k < 64; k++) {
            float4 m4 = *(const float4*)(Mcur + k * 68 + j0);
            float a0 = Asb[(i0 + 0) * 68 + k];
            float a1 = Asb[(i0 + 1) * 68 + k];
            float a2 = Asb[(i0 + 2) * 68 + k];
            float a3 = Asb[(i0 + 3) * 68 + k];
            acc[0][0] += a0 * m4.x; acc[0][1] += a0 * m4.y; acc[0][2] += a0 * m4.z; acc[0][3] += a0 * m4.w;
            acc[1][0] += a1 * m4.x; acc[1][1] += a1 * m4.y; acc[1][2] += a1 * m4.z; acc[1][3] += a1 * m4.w;
            acc[2][0] += a2 * m4.x; acc[2][1] += a2 * m4.y; acc[2][2] += a2 * m4.z; acc[2][3] += a2 * m4.w;
            acc[3][0] += a3 * m4.x; acc[3][1] += a3 * m4.y; acc[3][2] += a3 * m4.z; acc[3][3] += a3 * m4.w;
        }

        float vnew = 0.f;
        if (tid < 64) {
            vnew = Bxb[t * 128 + tid * 2] + Bxb[t * 128 + tid * 2 + 1];
#pragma unroll 4
            for (int k = 0; k < 64; k++)
                vnew += Asb[tid * 68 + k] * Mcur[k * 68 + 64];
        }

#pragma unroll
        for (int ii = 0; ii < 4; ii++)
            *(float4*)(Mnxt + (i0 + ii) * 68 + j0) =
                make_float4(acc[ii][0], acc[ii][1], acc[ii][2], acc[ii][3]);
        if (tid < 64) Mnxt[tid * 68 + 64] = vnew;
    }

    __syncthreads();
    const float* Mf = Ms1;
#pragma unroll
    for (int q = 0; q < 4; q++) {
        int o = (tid + 256 * q) * 4;
        *(float4*)(g_M + (size_t)chunk * 4096 + o) = *(const float4*)(Mf + (o >> 6) * 68 + (o & 63));
    }
    if (tid < 64) g_v[chunk * 64 + tid] = Mf[tid * 68 + 64];
}

// ================= Phase B: combine chunks (4 CTAs, 32 sequential steps) =================
__device__ __forceinline__ void bstep(
    float4 (&r)[4], int c, const float* __restrict__ Mbase,
    const float* __restrict__ vb, float* __restrict__ sb,
    float (*Mb)[64 * 68], float* hsm, float* psum, int tid, int i, int g)
{
    float* Ms_ = &Mb[c & 1][0];
#pragma unroll
    for (int q = 0; q < 4; q++) {
        int idx4 = tid + 256 * q;
        *(float4*)(Ms_ + (idx4 >> 4) * 68 + (idx4 & 15) * 4) = r[q];
    }
    __syncthreads();
    if (c + 2 < 32) {
        const float4* p = (const float4*)(Mbase + (size_t)(c + 2) * 4096);
#pragma unroll
        for (int q = 0; q < 4; q++) r[q] = p[tid + 256 * q];
    }
    if (tid < 64) sb[c * 64 + tid] = hsm[tid];
    float accv = 0.f;
    const float* mrow = Ms_ + i * 68 + g * 16;
#pragma unroll
    for (int u = 0; u < 4; u++) {
        float4 a  = *(const float4*)(mrow + u * 4);
        float4 h4 = *(const float4*)(hsm + g * 16 + u * 4);
        accv += a.x * h4.x + a.y * h4.y + a.z * h4.z + a.w * h4.w;
    }
    psum[i * 4 + g] = accv;
    __syncthreads();
    if (tid < 64) {
        float4 p4 = *(const float4*)(psum + tid * 4);
        hsm[tid] = (p4.x + p4.y) + (p4.z + p4.w) + vb[c * 64 + tid];
    }
}

__global__ __launch_bounds__(256) void scanB_kernel()
{
    __shared__ float Mb[2][64 * 68];
    __shared__ float hsm[64];
    __shared__ float psum[256];
    const int b = blockIdx.x, tid = threadIdx.x;
    const int i = tid & 63, g = tid >> 6;
    const float* Mbase = g_M + (size_t)b * 32 * 4096;
    const float* vb    = g_v + b * 32 * 64;
    float*       sb    = g_s + b * 32 * 64;
    if (tid < 64) hsm[tid] = 0.f;
    float4 r0[4], r1[4];
    {
        const float4* p0 = (const float4*)(Mbase);
        const float4* p1 = (const float4*)(Mbase + 4096);
#pragma unroll
        for (int q = 0; q < 4; q++) { r0[q] = p0[tid + 256 * q]; r1[q] = p1[tid + 256 * q]; }
    }
    for (int c = 0; c < 32; c += 2) {
        bstep(r0, c,     Mbase, vb, sb, Mb, hsm, psum, tid, i, g);
        bstep(r1, c + 1, Mbase, vb, sb, Mb, hsm, psum, tid, i, g);
    }
}

// ================= Phase C: within-chunk recurrence (128 CTAs x 32 steps) =================
__device__ __forceinline__ void cstep(
    float4 (&r)[4], int t, const float* __restrict__ Abase,
    const float* __restrict__ BxPb, float* __restrict__ ghb,
    float (*Abuf)[64 * 68], float* hsm, float* psum, int tid, int i, int g)
{
    float* Ab_s = &Abuf[t & 1][0];
#pragma unroll
    for (int q = 0; q < 4; q++) {
        int idx4 = tid + 256 * q;
        *(float4*)(Ab_s + (idx4 >> 4) * 68 + (idx4 & 15) * 4) = r[q];
    }
    __syncthreads();
    if (t + 2 < CHUNK) {
        const float4* p = (const float4*)(Abase + (size_t)(t + 2) * 4096);
#pragma unroll
        for (int q = 0; q < 4; q++) r[q] = p[tid + 256 * q];
    }
    float accv = 0.f;
    const float* arow = Ab_s + i * 68 + g * 16;
#pragma unroll
    for (int u = 0; u < 4; u++) {
        float4 a  = *(const float4*)(arow + u * 4);
        float4 h4 = *(const float4*)(hsm + g * 16 + u * 4);
        accv += a.x * h4.x + a.y * h4.y + a.z * h4.z + a.w * h4.w;
    }
    psum[i * 4 + g] = accv;
    __syncthreads();
    if (tid < 64) {
        float4 p4 = *(const float4*)(psum + tid * 4);
        float bx = BxPb[t * 128 + tid * 2] + BxPb[t * 128 + tid * 2 + 1];
        float hv = (p4.x + p4.y) + (p4.z + p4.w) + bx;
        hsm[tid] = hv;
        ghb[t * DST + tid] = hv;
    }
}

__global__ __launch_bounds__(256) void scanC_kernel()
{
    __shared__ float Abuf[2][64 * 68];
    __shared__ float hsm[64];
    __shared__ float psum[256];
    const int chunk = blockIdx.x, tid = threadIdx.x;
    const int i = tid & 63, g = tid >> 6;
    const int token0 = chunk * CHUNK;
    const float* Abase = g_A + (size_t)token0 * 4096;
    const float* BxPb  = g_BxPart + (size_t)token0 * 128;
    float*       ghb   = g_h + (size_t)token0 * DST;

    if (tid < 64) hsm[tid] = g_s[chunk * 64 + tid];

    float4 r0[4], r1[4];
    {
        const float4* p0 = (const float4*)(Abase);
        const float4* p1 = (const float4*)(Abase + 4096);
#pragma unroll
        for (int q = 0; q < 4; q++) { r0[q] = p0[tid + 256 * q]; r1[q] = p1[tid + 256 * q]; }
    }
    for (int t = 0; t < CHUNK; t += 2) {
        cstep(r0, t,     Abase, BxPb, ghb, Abuf, hsm, psum, tid, i, g);
        cstep(r1, t + 1, Abase, BxPb, ghb, Abuf, hsm, psum, tid, i, g);
    }
}

// ---------------- launch ----------------
extern "C" void kernel_launch(void* const* d_in, const int* in_sizes, int n_in,
                              void* d_out, int out_size)
{
    const float* x  = (const float*)d_in[0];
    const float* WA = (const float*)d_in[1];
    const float* bA = (const float*)d_in[2];
    const float* WB = (const float*)d_in[3];
    const float* bB = (const float*)d_in[4];
    const float* WC = (const float*)d_in[5];
    const float* bC = (const float*)d_in[6];
    const float* WD = (const float*)d_in[7];
    const float* bD = (const float*)d_in[8];
    // d_in[9]/d_in[10] (Wdelta, bdelta): reference computes-then-discards delta -> skipped.
    float* out = (float*)d_out;

    dim3 blk(256);
    const int scanA_smem = 4 * 64 * 68 * (int)sizeof(float);
    cudaFuncSetAttribute(scanA_kernel, cudaFuncAttributeMaxDynamicSharedMemorySize, scanA_smem);

    // 1) expD (needed by A epilogue)
    expd_kernel<<<NTOK / 4, blk>>>(x, WD, bD);
    // 2) Bx partials fused into WB-GEMM epilogue (Bm never materialized)
    gemm_kernel<2, 16384, 8><<<dim3(128, 32), blk>>>(x, WB, bB, nullptr);
    // 3) A = (x@WA + bA)*expD
    gemm_kernel<1, 4096, 8><<<dim3(32, 32), blk>>>(x, WA, bA, nullptr);
    // 4) chunked scan: A (chunk matrices) -> B (combine) -> C (within-chunk states)
    scanA_kernel<<<NCHUNK, blk, scanA_smem>>>();
    scanB_kernel<<<BATCH, blk>>>();
    scanC_kernel<<<NCHUNK, blk>>>();
    // 5) out = (h (x) x) @ WCr + h@bC  — Cm never materialized
    gemm_kernel<4, 256, 4><<<dim3(2, 64), blk>>>(x, WC, bC, out);
}

// round 8
// speedup vs baseline: 2.2545x; 1.7243x over previous
#include <cuda_runtime.h>
#include <cuda_bf16.h>
#include <stdint.h>
#include <math.h>

#define BATCH 4
#define SEQ   1024
#define DMOD  256
#define DST   64
#define NTOK  4096
#define CHUNK 32
#define NCHUNK 128

// ---------------- scratch (static __device__ — referenced ONLY from device code) ----
__device__ float g_A[NTOK * DST * DST];     // 64 MB scaled A
__device__ float g_expD[NTOK * DST];
__device__ float g_BxPart[NTOK * 256];      // [token][n*4+p]
__device__ float g_h[NTOK * DST];
__device__ float g_M[NCHUNK * DST * DST];
__device__ float g_v[NCHUNK * DST];
__device__ float g_s[NCHUNK * DST];

// bf16 hi/lo splits (prep kernels fill these)
__device__ __nv_bfloat16 g_Xhi[NTOK * DMOD],   g_Xlo[NTOK * DMOD];
__device__ __nv_bfloat16 g_WBThi[16384 * 256], g_WBTlo[16384 * 256];   // WB^T [n][k]
__device__ __nv_bfloat16 g_WAThi[4096 * 256],  g_WATlo[4096 * 256];    // WA^T [n][k]
__device__ __nv_bfloat16 g_WCThi[256 * 16448], g_WCTlo[256 * 16448];   // remapped WC^T

// ---------------- helpers ----------------
__device__ __forceinline__ void bf16_split(float v, __nv_bfloat16& hi, __nv_bfloat16& lo) {
    hi = __float2bfloat16(v);
    lo = __float2bfloat16(v - __bfloat162float(hi));
}
__device__ __forceinline__ void mma16816(float* d, const unsigned* a, const unsigned* b) {
    asm volatile("mma.sync.aligned.m16n8k16.row.col.f32.bf16.bf16.f32 "
        "{%0,%1,%2,%3},{%4,%5,%6,%7},{%8,%9},{%0,%1,%2,%3};"
        : "+f"(d[0]), "+f"(d[1]), "+f"(d[2]), "+f"(d[3])
        : "r"(a[0]), "r"(a[1]), "r"(a[2]), "r"(a[3]), "r"(b[0]), "r"(b[1]));
}

// ---------------- prep kernels ----------------
__global__ __launch_bounds__(256) void split_x_kernel(const float* __restrict__ X) {
    int i = (blockIdx.x * 256 + threadIdx.x) * 4;
    float4 v = *(const float4*)(X + i);
    __nv_bfloat16 h0,l0,h1,l1,h2,l2,h3,l3;
    bf16_split(v.x,h0,l0); bf16_split(v.y,h1,l1); bf16_split(v.z,h2,l2); bf16_split(v.w,h3,l3);
    __nv_bfloat162 a,b; a.x=h0; a.y=h1; b.x=h2; b.y=h3;
    *(__nv_bfloat162*)(g_Xhi + i) = a; *(__nv_bfloat162*)(g_Xhi + i + 2) = b;
    a.x=l0; a.y=l1; b.x=l2; b.y=l3;
    *(__nv_bfloat162*)(g_Xlo + i) = a; *(__nv_bfloat162*)(g_Xlo + i + 2) = b;
}

// in[256][N] fp32 -> g_W{B,A}T [N][256] bf16 hi/lo.  DEST: 0 = WB, 1 = WA.
template<int DEST>
__global__ void transpose_split_kernel(const float* __restrict__ in, int N)
{
    __nv_bfloat16* outHi = (DEST == 0) ? g_WBThi : g_WAThi;
    __nv_bfloat16* outLo = (DEST == 0) ? g_WBTlo : g_WATlo;
    __shared__ float tile[32][33];
    int n0 = blockIdx.x * 32, k0 = blockIdx.y * 32;
    int tx = threadIdx.x, ty = threadIdx.y;
#pragma unroll
    for (int j = 0; j < 4; j++)
        tile[ty + j*8][tx] = in[(size_t)(k0 + ty + j*8) * N + n0 + tx];
    __syncthreads();
#pragma unroll
    for (int j = 0; j < 4; j++) {
        float v = tile[tx][ty + j*8];
        __nv_bfloat16 h, l; bf16_split(v, h, l);
        size_t o = (size_t)(n0 + ty + j*8) * 256 + k0 + tx;
        outHi[o] = h; outLo[o] = l;
    }
}

// WCT[d][n*256+kk] = WC[kk][n*256+d]
__global__ void wc_remap_kernel(const float* __restrict__ WC) {
    __shared__ float tile[32][33];
    int kk0 = blockIdx.x * 32, d0 = blockIdx.y * 32, n = blockIdx.z;
    int tx = threadIdx.x, ty = threadIdx.y;
#pragma unroll
    for (int j = 0; j < 4; j++)
        tile[ty + j*8][tx] = WC[(size_t)(kk0 + ty + j*8) * 16384 + n*256 + d0 + tx];
    __syncthreads();
#pragma unroll
    for (int j = 0; j < 4; j++) {
        float v = tile[tx][ty + j*8];
        __nv_bfloat16 h, l; bf16_split(v, h, l);
        size_t o = (size_t)(d0 + ty + j*8) * 16448 + n*256 + kk0 + tx;
        g_WCThi[o] = h; g_WCTlo[o] = l;
    }
}

// WCT[d][16384+n] = bC[n*256+d]
__global__ __launch_bounds__(256) void wc_bias_kernel(const float* __restrict__ bC) {
    int n = blockIdx.x, d = threadIdx.x;
    float v = bC[n * 256 + d];
    __nv_bfloat16 h, l; bf16_split(v, h, l);
    g_WCThi[(size_t)d * 16448 + 16384 + n] = h;
    g_WCTlo[(size_t)d * 16448 + 16384 + n] = l;
}

// ---------------- tensor-core GEMM (bf16 split-3, mma.sync, direct LDS frags) ----
// CTA tile 128x64, K-chunk 32, smem row stride 40 (<48KB total, no opt-in needed).
// 8 warps: 4(m) x 2(n); warp tile 32x32 = 2 m16 x 4 n8.
// Fragment loads are plain 32-bit LDS per the PTX fragment tables (no ldmatrix).
// B operand selected INSIDE device code by MODE (no __device__ symbol passed from host).
// MODE 1: g_A = (X@WA + bA)*expD         (g_WAT, KS=256)
// MODE 2: Bx partials from (X@WB + bB)   (g_WBT, KS=256; Bm never stored)
// MODE 4: out = Y@WCr (bias folded)      (g_WCT, KS=16448; Y=h(x)x on the fly)
#define ASTR 40
template<int MODE, int KS>
__global__ __launch_bounds__(256)
void tgemm(const float* __restrict__ X, const float* __restrict__ bias, float* __restrict__ Out)
{
    const __nv_bfloat16* __restrict__ BThi =
        (MODE == 1) ? g_WAThi : (MODE == 2) ? g_WBThi : g_WCThi;
    const __nv_bfloat16* __restrict__ BTlo =
        (MODE == 1) ? g_WATlo : (MODE == 2) ? g_WBTlo : g_WCTlo;

    extern __shared__ char smemraw[];
    __nv_bfloat16* sAh = (__nv_bfloat16*)smemraw;        // [128][40]
    __nv_bfloat16* sAl = sAh + 128 * ASTR;
    __nv_bfloat16* sBh = sAl + 128 * ASTR;               // [64][40]
    __nv_bfloat16* sBl = sBh + 64 * ASTR;                // ends at 30720 B
    float* Cs  = (float*)smemraw;                        // epilogue reuse [128][68]
    float* Red = (float*)(smemraw + 128 * 68 * 4);       // [128][16] (MODE 2)

    const int tid  = threadIdx.x;
    const int lane = tid & 31;
    const int warp = tid >> 5;
    const int wm   = warp >> 1;      // 0..3
    const int wn   = warp & 1;       // 0..1
    const int t0   = blockIdx.y * 128;
    const int c0   = blockIdx.x * 64;
    const int lg   = lane >> 2;      // groupID 0..7
    const int lt2  = (lane & 3) * 2; // threadID_in_group*2

    float acc[2][4][4];
#pragma unroll
    for (int mt = 0; mt < 2; mt++)
#pragma unroll
        for (int nt = 0; nt < 4; nt++)
#pragma unroll
            for (int j = 0; j < 4; j++) acc[mt][nt][j] = 0.f;

    constexpr int KTOT = (MODE == 4) ? 16448 : 256;

    for (int k0 = 0; k0 < KTOT; k0 += 32) {
        // ---- A tile: 128 x 32 bf16 (hi & lo) ----
        if constexpr (MODE == 4) {
            const int nblk = k0 >> 8;
#pragma unroll
            for (int q = 0; q < 4; q++) {
                int ii = tid + 256 * q;          // 0..1023
                int m = ii >> 3, c4 = (ii & 7) * 4;
                int t = t0 + m;
                float4 v4;
                if (k0 < 16384) {
                    float hv = g_h[t * DST + nblk];
                    v4 = *(const float4*)(X + t * DMOD + (k0 & 255) + c4);
                    v4.x *= hv; v4.y *= hv; v4.z *= hv; v4.w *= hv;
                } else {
                    v4 = *(const float4*)(g_h + t * DST + (k0 - 16384) + c4);
                }
                __nv_bfloat16 h0,l0,h1,l1,h2,l2,h3,l3;
                bf16_split(v4.x,h0,l0); bf16_split(v4.y,h1,l1);
                bf16_split(v4.z,h2,l2); bf16_split(v4.w,h3,l3);
                __nv_bfloat162 p0,p1; p0.x=h0; p0.y=h1; p1.x=h2; p1.y=h3;
                *(__nv_bfloat162*)(sAh + m*ASTR + c4)     = p0;
                *(__nv_bfloat162*)(sAh + m*ASTR + c4 + 2) = p1;
                p0.x=l0; p0.y=l1; p1.x=l2; p1.y=l3;
                *(__nv_bfloat162*)(sAl + m*ASTR + c4)     = p0;
                *(__nv_bfloat162*)(sAl + m*ASTR + c4 + 2) = p1;
            }
        } else {
#pragma unroll
            for (int q = 0; q < 2; q++) {
                int idx = tid + 256 * q;         // 0..511
                int m = idx >> 2, w = idx & 3;
                *(uint4*)(sAh + m*ASTR + w*8) = *(const uint4*)(g_Xhi + (t0+m)*DMOD + k0 + w*8);
                *(uint4*)(sAl + m*ASTR + w*8) = *(const uint4*)(g_Xlo + (t0+m)*DMOD + k0 + w*8);
            }
        }
        // ---- B tile: 64 x 32 (BT is [n][k] row-major) ----
        {
            int n = tid >> 2, w = tid & 3;
            *(uint4*)(sBh + n*ASTR + w*8) = *(const uint4*)(BThi + (size_t)(c0+n)*KS + k0 + w*8);
            *(uint4*)(sBl + n*ASTR + w*8) = *(const uint4*)(BTlo + (size_t)(c0+n)*KS + k0 + w*8);
        }
        __syncthreads();

#pragma unroll
        for (int ks = 0; ks < 2; ks++) {
            const int k = ks * 16;
            unsigned ah[2][4], al[2][4];
#pragma unroll
            for (int mt = 0; mt < 2; mt++) {
                const int r = wm*32 + mt*16 + lg;
                ah[mt][0] = *(const unsigned*)(sAh + r*ASTR + k + lt2);
                ah[mt][1] = *(const unsigned*)(sAh + (r+8)*ASTR + k + lt2);
                ah[mt][2] = *(const unsigned*)(sAh + r*ASTR + k + 8 + lt2);
                ah[mt][3] = *(const unsigned*)(sAh + (r+8)*ASTR + k + 8 + lt2);
                al[mt][0] = *(const unsigned*)(sAl + r*ASTR + k + lt2);
                al[mt][1] = *(const unsigned*)(sAl + (r+8)*ASTR + k + lt2);
                al[mt][2] = *(const unsigned*)(sAl + r*ASTR + k + 8 + lt2);
                al[mt][3] = *(const unsigned*)(sAl + (r+8)*ASTR + k + 8 + lt2);
            }
            unsigned bh[4][2], bl[4][2];
#pragma unroll
            for (int nt = 0; nt < 4; nt++) {
                const int n = wn*32 + nt*8 + lg;
                bh[nt][0] = *(const unsigned*)(sBh + n*ASTR + k + lt2);
                bh[nt][1] = *(const unsigned*)(sBh + n*ASTR + k + 8 + lt2);
                bl[nt][0] = *(const unsigned*)(sBl + n*ASTR + k + lt2);
                bl[nt][1] = *(const unsigned*)(sBl + n*ASTR + k + 8 + lt2);
            }
#pragma unroll
            for (int mt = 0; mt < 2; mt++)
#pragma unroll
                for (int nt = 0; nt < 4; nt++) {
                    mma16816(acc[mt][nt], ah[mt], bh[nt]);
                    mma16816(acc[mt][nt], ah[mt], bl[nt]);
                    mma16816(acc[mt][nt], al[mt], bh[nt]);
                }
        }
        __syncthreads();
    }

    // ---- stage accumulators to smem for clean epilogues ----
#pragma unroll
    for (int mt = 0; mt < 2; mt++)
#pragma unroll
        for (int nt = 0; nt < 4; nt++) {
            int r = wm*32 + mt*16 + lg;
            int c = wn*32 + nt*8 + lt2;
            Cs[r*68 + c]       = acc[mt][nt][0];
            Cs[r*68 + c + 1]   = acc[mt][nt][1];
            Cs[(r+8)*68 + c]   = acc[mt][nt][2];
            Cs[(r+8)*68 + c+1] = acc[mt][nt][3];
        }
    __syncthreads();

    const int tx = tid & 15, ty = tid >> 4;

    if constexpr (MODE == 1) {
        float4 bb = *(const float4*)(bias + c0 + tx*4);
        const int i0 = c0 >> 6;
#pragma unroll
        for (int rr = 0; rr < 8; rr++) {
            int row = (rr & 3) + ty*4 + (rr >> 2) * 64;
            int t = t0 + row;
            float s = g_expD[t * DST + i0];
            const float* cp = Cs + row*68 + tx*4;
            float4 v = make_float4((cp[0]+bb.x)*s, (cp[1]+bb.y)*s, (cp[2]+bb.z)*s, (cp[3]+bb.w)*s);
            *(float4*)(g_A + (size_t)t*4096 + c0 + tx*4) = v;
        }
    } else if constexpr (MODE == 2) {
        float4 bb = *(const float4*)(bias + c0 + tx*4);
        const int d0 = (c0 & 255) + tx*4;
#pragma unroll
        for (int rr = 0; rr < 8; rr++) {
            int row = (rr & 3) + ty*4 + (rr >> 2) * 64;
            int t = t0 + row;
            float4 xv = *(const float4*)(X + t*DMOD + d0);
            const float* cp = Cs + row*68 + tx*4;
            Red[row*16 + tx] = (cp[0]+bb.x)*xv.x + (cp[1]+bb.y)*xv.y
                             + (cp[2]+bb.z)*xv.z + (cp[3]+bb.w)*xv.w;
        }
        __syncthreads();
        if (tid < 128) {
            float s = 0.f;
#pragma unroll
            for (int q = 0; q < 16; q++) s += Red[tid*16 + q];
            g_BxPart[(t0 + tid)*256 + ((c0 >> 8) << 2) + ((c0 >> 6) & 3)] = s;
        }
    } else {   // MODE 4
#pragma unroll
        for (int rr = 0; rr < 8; rr++) {
            int row = (rr & 3) + ty*4 + (rr >> 2) * 64;
            int t = t0 + row;
            const float* cp = Cs + row*68 + tx*4;
            *(float4*)(Out + (size_t)t*DMOD + c0 + tx*4) = make_float4(cp[0], cp[1], cp[2], cp[3]);
        }
    }
}

// ---------------- expD = exp(x@WD + bD) ----------------
__global__ __launch_bounds__(256) void expd_kernel(const float* __restrict__ X,
                                                   const float* __restrict__ WD,
                                                   const float* __restrict__ bD)
{
    __shared__ float xs[4][256];
    const int tid = threadIdx.x;
    const int t0  = blockIdx.x * 4;
    {
        int r = tid >> 6, c4 = (tid & 63) * 4;
        *(float4*)(&xs[r][c4]) = *(const float4*)(X + (t0 + r) * DMOD + c4);
    }
    __syncthreads();
    const int tt = tid >> 6;
    const int c  = tid & 63;
    float acc = bD[c];
#pragma unroll 8
    for (int k = 0; k < DMOD; k++) acc += xs[tt][k] * WD[k * DST + c];
    g_expD[(t0 + tt) * DST + c] = expf(acc);
}

// ================= Phase A: per-chunk transition matrices =================
__global__ __launch_bounds__(256) void scanA_kernel()
{
    extern __shared__ float sm[];
    float* As0 = sm;
    float* As1 = sm + 64 * 68;
    float* Ms0 = sm + 2 * 64 * 68;
    float* Ms1 = sm + 3 * 64 * 68;

    const int chunk  = blockIdx.x;
    const int tid    = threadIdx.x;
    const int token0 = chunk * CHUNK;
    const float* Ab  = g_A + (size_t)token0 * 4096;
    const float* Bxb = g_BxPart + (size_t)token0 * 256;

    const int i0 = (tid >> 4) * 4;
    const int j0 = (tid & 15) * 4;

#pragma unroll
    for (int q = 0; q < 4; q++) {
        int o = (tid + 256 * q) * 4;
        *(float4*)(Ms0 + (o >> 6) * 68 + (o & 63)) = *(const float4*)(Ab + o);
    }
    if (tid < 64) {
        float4 b4 = *(const float4*)(Bxb + tid * 4);
        Ms0[tid * 68 + 64] = (b4.x + b4.y) + (b4.z + b4.w);
    }

    float4 r[4];
#pragma unroll
    for (int q = 0; q < 4; q++) r[q] = *(const float4*)(Ab + 4096 + (tid + 256 * q) * 4);

    for (int t = 1; t < CHUNK; t++) {
        float* Asb        = (t & 1) ? As1 : As0;
        const float* Mcur = ((t - 1) & 1) ? Ms1 : Ms0;
        float* Mnxt       = (t & 1) ? Ms1 : Ms0;

#pragma unroll
        for (int q = 0; q < 4; q++) {
            int o = (tid + 256 * q) * 4;
            *(float4*)(Asb + (o >> 6) * 68 + (o & 63)) = r[q];
        }
        __syncthreads();
        if (t + 1 < CHUNK) {
#pragma unroll
            for (int q = 0; q < 4; q++)
                r[q] = *(const float4*)(Ab + (size_t)(t + 1) * 4096 + (tid + 256 * q) * 4);
        }

        float acc[4][4];
#pragma unroll
        for (int ii = 0; ii < 4; ii++)
#pragma unroll
            for (int jj = 0; jj < 4; jj++) acc[ii][jj] = 0.f;

#pragma unroll 4
        for (int k = 0; k < 64; k++) {
            float4 m4 = *(const float4*)(Mcur + k * 68 + j0);
            float a0 = Asb[(i0 + 0) * 68 + k];
            float a1 = Asb[(i0 + 1) * 68 + k];
            float a2 = Asb[(i0 + 2) * 68 + k];
            float a3 = Asb[(i0 + 3) * 68 + k];
            acc[0][0] += a0 * m4.x; acc[0][1] += a0 * m4.y; acc[0][2] += a0 * m4.z; acc[0][3] += a0 * m4.w;
            acc[1][0] += a1 * m4.x; acc[1][1] += a1 * m4.y; acc[1][2] += a1 * m4.z; acc[1][3] += a1 * m4.w;
            acc[2][0] += a2 * m4.x; acc[2][1] += a2 * m4.y; acc[2][2] += a2 * m4.z; acc[2][3] += a2 * m4.w;
            acc[3][0] += a3 * m4.x; acc[3][1] += a3 * m4.y; acc[3][2] += a3 * m4.z; acc[3][3] += a3 * m4.w;
        }

        float vnew = 0.f;
        if (tid < 64) {
            float4 b4 = *(const float4*)(Bxb + t * 256 + tid * 4);
            vnew = (b4.x + b4.y) + (b4.z + b4.w);
#pragma unroll 4
            for (int k = 0; k < 64; k++)
                vnew += Asb[tid * 68 + k] * Mcur[k * 68 + 64];
        }

#pragma unroll
        for (int ii = 0; ii < 4; ii++)
            *(float4*)(Mnxt + (i0 + ii) * 68 + j0) =
                make_float4(acc[ii][0], acc[ii][1], acc[ii][2], acc[ii][3]);
        if (tid < 64) Mnxt[tid * 68 + 64] = vnew;
    }

    __syncthreads();
    const float* Mf = Ms1;
#pragma unroll
    for (int q = 0; q < 4; q++) {
        int o = (tid + 256 * q) * 4;
        *(float4*)(g_M + (size_t)chunk * 4096 + o) = *(const float4*)(Mf + (o >> 6) * 68 + (o & 63));
    }
    if (tid < 64) g_v[chunk * 64 + tid] = Mf[tid * 68 + 64];
}

// ================= Phase B: combine chunks =================
__device__ __forceinline__ void bstep(
    float4 (&r)[4], int c, const float* __restrict__ Mbase,
    const float* __restrict__ vb, float* __restrict__ sb,
    float (*Mb)[64 * 68], float* hsm, float* psum, int tid, int i, int g)
{
    float* Ms_ = &Mb[c & 1][0];
#pragma unroll
    for (int q = 0; q < 4; q++) {
        int idx4 = tid + 256 * q;
        *(float4*)(Ms_ + (idx4 >> 4) * 68 + (idx4 & 15) * 4) = r[q];
    }
    __syncthreads();
    if (c + 2 < 32) {
        const float4* p = (const float4*)(Mbase + (size_t)(c + 2) * 4096);
#pragma unroll
        for (int q = 0; q < 4; q++) r[q] = p[tid + 256 * q];
    }
    if (tid < 64) sb[c * 64 + tid] = hsm[tid];
    float accv = 0.f;
    const float* mrow = Ms_ + i * 68 + g * 16;
#pragma unroll
    for (int u = 0; u < 4; u++) {
        float4 a  = *(const float4*)(mrow + u * 4);
        float4 h4 = *(const float4*)(hsm + g * 16 + u * 4);
        accv += a.x * h4.x + a.y * h4.y + a.z * h4.z + a.w * h4.w;
    }
    psum[i * 4 + g] = accv;
    __syncthreads();
    if (tid < 64) {
        float4 p4 = *(const float4*)(psum + tid * 4);
        hsm[tid] = (p4.x + p4.y) + (p4.z + p4.w) + vb[c * 64 + tid];
    }
}

__global__ __launch_bounds__(256) void scanB_kernel()
{
    __shared__ float Mb[2][64 * 68];
    __shared__ float hsm[64];
    __shared__ float psum[256];
    const int b = blockIdx.x, tid = threadIdx.x;
    const int i = tid & 63, g = tid >> 6;
    const float* Mbase = g_M + (size_t)b * 32 * 4096;
    const float* vb    = g_v + b * 32 * 64;
    float*       sb    = g_s + b * 32 * 64;
    if (tid < 64) hsm[tid] = 0.f;
    float4 r0[4], r1[4];
    {
        const float4* p0 = (const float4*)(Mbase);
        const float4* p1 = (const float4*)(Mbase + 4096);
#pragma unroll
        for (int q = 0; q < 4; q++) { r0[q] = p0[tid + 256 * q]; r1[q] = p1[tid + 256 * q]; }
    }
    for (int c = 0; c < 32; c += 2) {
        bstep(r0, c,     Mbase, vb, sb, Mb, hsm, psum, tid, i, g);
        bstep(r1, c + 1, Mbase, vb, sb, Mb, hsm, psum, tid, i, g);
    }
}

// ================= Phase C: within-chunk recurrence =================
__device__ __forceinline__ void cstep(
    float4 (&r)[4], int t, const float* __restrict__ Abase,
    const float* __restrict__ BxPb, float* __restrict__ ghb,
    float (*Abuf)[64 * 68], float* hsm, float* psum, int tid, int i, int g)
{
    float* Ab_s = &Abuf[t & 1][0];
#pragma unroll
    for (int q = 0; q < 4; q++) {
        int idx4 = tid + 256 * q;
        *(float4*)(Ab_s + (idx4 >> 4) * 68 + (idx4 & 15) * 4) = r[q];
    }
    __syncthreads();
    if (t + 2 < CHUNK) {
        const float4* p = (const float4*)(Abase + (size_t)(t + 2) * 4096);
#pragma unroll
        for (int q = 0; q < 4; q++) r[q] = p[tid + 256 * q];
    }
    float accv = 0.f;
    const float* arow = Ab_s + i * 68 + g * 16;
#pragma unroll
    for (int u = 0; u < 4; u++) {
        float4 a  = *(const float4*)(arow + u * 4);
        float4 h4 = *(const float4*)(hsm + g * 16 + u * 4);
        accv += a.x * h4.x + a.y * h4.y + a.z * h4.z + a.w * h4.w;
    }
    psum[i * 4 + g] = accv;
    __syncthreads();
    if (tid < 64) {
        float4 p4 = *(const float4*)(psum + tid * 4);
        float4 b4 = *(const float4*)(BxPb + t * 256 + tid * 4);
        float hv = (p4.x + p4.y) + (p4.z + p4.w) + (b4.x + b4.y) + (b4.z + b4.w);
        hsm[tid] = hv;
        ghb[t * DST + tid] = hv;
    }
}

__global__ __launch_bounds__(256) void scanC_kernel()
{
    __shared__ float Abuf[2][64 * 68];
    __shared__ float hsm[64];
    __shared__ float psum[256];
    const int chunk = blockIdx.x, tid = threadIdx.x;
    const int i = tid & 63, g = tid >> 6;
    const int token0 = chunk * CHUNK;
    const float* Abase = g_A + (size_t)token0 * 4096;
    const float* BxPb  = g_BxPart + (size_t)token0 * 256;
    float*       ghb   = g_h + (size_t)token0 * DST;

    if (tid < 64) hsm[tid] = g_s[chunk * 64 + tid];

    float4 r0[4], r1[4];
    {
        const float4* p0 = (const float4*)(Abase);
        const float4* p1 = (const float4*)(Abase + 4096);
#pragma unroll
        for (int q = 0; q < 4; q++) { r0[q] = p0[tid + 256 * q]; r1[q] = p1[tid + 256 * q]; }
    }
    for (int t = 0; t < CHUNK; t += 2) {
        cstep(r0, t,     Abase, BxPb, ghb, Abuf, hsm, psum, tid, i, g);
        cstep(r1, t + 1, Abase, BxPb, ghb, Abuf, hsm, psum, tid, i, g);
    }
}

// ---------------- launch ----------------
extern "C" void kernel_launch(void* const* d_in, const int* in_sizes, int n_in,
                              void* d_out, int out_size)
{
    const float* x  = (const float*)d_in[0];
    const float* WA = (const float*)d_in[1];
    const float* bA = (const float*)d_in[2];
    const float* WB = (const float*)d_in[3];
    const float* bB = (const float*)d_in[4];
    const float* WC = (const float*)d_in[5];
    const float* bC = (const float*)d_in[6];
    const float* WD = (const float*)d_in[7];
    const float* bD = (const float*)d_in[8];
    // d_in[9]/d_in[10] (Wdelta, bdelta): reference computes-then-discards delta -> skipped.
    float* out = (float*)d_out;

    dim3 blk(256);
    const int tg_smem    = 128 * 68 * 4 + 128 * 16 * 4;        // 43008 B (< 48KB: no opt-in)
    const int scanA_smem = 4 * 64 * 68 * (int)sizeof(float);   // 69632 B
    cudaFuncSetAttribute(scanA_kernel, cudaFuncAttributeMaxDynamicSharedMemorySize, scanA_smem);

    // prep: bf16 hi/lo splits (+ transposes / remap) — all device-global targets
    // are referenced inside the kernels (never passed from host).
    split_x_kernel<<<NTOK * DMOD / 1024, blk>>>(x);
    transpose_split_kernel<0><<<dim3(512, 8), dim3(32, 8)>>>(WB, 16384);
    transpose_split_kernel<1><<<dim3(128, 8), dim3(32, 8)>>>(WA, 4096);
    wc_remap_kernel<<<dim3(8, 8, 64), dim3(32, 8)>>>(WC);
    wc_bias_kernel<<<64, blk>>>(bC);

    // expD (needed by A epilogue)
    expd_kernel<<<NTOK / 4, blk>>>(x, WD, bD);
    // Bx partials fused into WB-GEMM epilogue (Bm never materialized)
    tgemm<2, 256><<<dim3(256, 32), blk, tg_smem>>>(x, bB, nullptr);
    // A = (x@WA + bA)*expD
    tgemm<1, 256><<<dim3(64, 32), blk, tg_smem>>>(x, bA, nullptr);
    // chunked scan
    scanA_kernel<<<NCHUNK, blk, scanA_smem>>>();
    scanB_kernel<<<BATCH, blk>>>();
    scanC_kernel<<<NCHUNK, blk>>>();
    // out = (h (x) x) @ WCr (+ h@bC folded) — Cm never materialized
    tgemm<4, 16448><<<dim3(4, 32), blk, tg_smem>>>(x, nullptr, out);
}